// round 10
// baseline (speedup 1.0000x reference)
#include <cuda_runtime.h>
#include <cstdint>

#define NPTS 16384
#define NB   8
#define NP   1024
#define CIN  32
#define CSZ  8                 // FPS cluster size (CTAs per batch-pair)
#define SLICE (NPTS/CSZ)       // 2048 points per CTA per batch
#define FTH  512               // FPS threads per CTA
#define PPT  (SLICE/FTH)       // 4 points per thread per batch
#define NW   (FTH/32)          // 16 warps

// ---------------- scratch (static __device__, no allocation) ----------------
__device__ float g_xs[NB*NPTS], g_ys[NB*NPTS], g_zs[NB*NPTS], g_xn[NB*NPTS];
__device__ float g_qx[NB*NP], g_qy[NB*NP], g_qz[NB*NP], g_qn[NB*NP];
__device__ int   g_idx0[NB*NP*16];
__device__ int   g_idx1[NB*NP*32];
__device__ float g_w0p[32*36];   // branch0 L1 weights padded 35->36
__device__ float g_w1p[64*36];   // branch1 L1 weights padded 35->36

// ---------------- packed f32x2 helpers (Blackwell) ----------------
__device__ __forceinline__ unsigned long long pk2(float a, float b){
  unsigned long long r; asm("mov.b64 %0,{%1,%2};" : "=l"(r) : "f"(a), "f"(b)); return r;
}
__device__ __forceinline__ void upk2(unsigned long long v, float& a, float& b){
  asm("mov.b64 {%0,%1},%2;" : "=f"(a), "=f"(b) : "l"(v));
}
__device__ __forceinline__ unsigned long long add2(unsigned long long a, unsigned long long b){
  unsigned long long r; asm("add.rn.f32x2 %0,%1,%2;" : "=l"(r) : "l"(a), "l"(b)); return r;
}
__device__ __forceinline__ unsigned long long mul2(unsigned long long a, unsigned long long b){
  unsigned long long r; asm("mul.rn.f32x2 %0,%1,%2;" : "=l"(r) : "l"(a), "l"(b)); return r;
}
__device__ __forceinline__ unsigned long long fma2(unsigned long long a, unsigned long long b,
                                                  unsigned long long c){
  unsigned long long r; asm("fma.rn.f32x2 %0,%1,%2,%3;" : "=l"(r) : "l"(a), "l"(b), "l"(c));
  return r;
}

// ---------------- cluster / mbarrier helpers ----------------
__device__ __forceinline__ uint32_t smem_u32(const void* p){
  return (uint32_t)__cvta_generic_to_shared(p);
}
__device__ __forceinline__ uint32_t mapa_rank(uint32_t laddr, uint32_t rank){
  uint32_t r; asm("mapa.shared::cluster.u32 %0, %1, %2;" : "=r"(r) : "r"(laddr), "r"(rank));
  return r;
}
__device__ __forceinline__ void st_cl_u64(uint32_t addr, unsigned long long v){
  asm volatile("st.shared::cluster.u64 [%0], %1;" :: "r"(addr), "l"(v) : "memory");
}
__device__ __forceinline__ void mbar_init(uint32_t addr, uint32_t cnt){
  asm volatile("mbarrier.init.shared.b64 [%0], %1;" :: "r"(addr), "r"(cnt) : "memory");
}
__device__ __forceinline__ void mbar_arrive_rel_cluster(uint32_t addr){
  asm volatile("mbarrier.arrive.release.cluster.shared::cluster.b64 _, [%0];"
               :: "r"(addr) : "memory");
}
__device__ __forceinline__ void mbar_wait_acq_cta(uint32_t addr, uint32_t parity){
  asm volatile(
    "{\n\t.reg .pred P;\n\t"
    "WL_%=:\n\t"
    "mbarrier.try_wait.parity.acquire.cta.shared::cta.b64 P, [%0], %1, 0x989680;\n\t"
    "@!P bra WL_%=;\n\t"
    "}" :: "r"(addr), "r"(parity) : "memory");
}
__device__ __forceinline__ void cluster_sync_all(){
  asm volatile("barrier.cluster.arrive.aligned;" ::: "memory");
  asm volatile("barrier.cluster.wait.aligned;" ::: "memory");
}
__device__ __forceinline__ uint32_t ctarank(){
  uint32_t r; asm("mov.u32 %0, %%cluster_ctarank;" : "=r"(r)); return r;
}

// ---------------- prep: AoS->SoA + squared norms ----------------
__global__ void prep_soa(const float* __restrict__ xyz){
  int i = blockIdx.x*blockDim.x + threadIdx.x;
  if (i >= NB*NPTS) return;
  float x = xyz[3*i+0], y = xyz[3*i+1], z = xyz[3*i+2];
  g_xs[i]=x; g_ys[i]=y; g_zs[i]=z;
  g_xn[i] = __fadd_rn(__fadd_rn(__fmul_rn(x,x), __fmul_rn(y,y)), __fmul_rn(z,z));
}

// ---------------- prep: pad L1 weight rows 35 -> 36 ----------------
__global__ void prep_w(const float* __restrict__ w00, const float* __restrict__ w10){
  int t = threadIdx.x;
  for (int i=t; i<32*36; i+=256){ int o=i/36, c=i-o*36; g_w0p[i] = (c<35) ? w00[o*35+c] : 0.f; }
  for (int i=t; i<64*36; i+=256){ int o=i/36, c=i-o*36; g_w1p[i] = (c<35) ? w10[o*35+c] : 0.f; }
}

// ---------------- FPS: 8-CTA cluster, TWO interleaved batches (latency hiding) ----------------
// Two independent FPS chains (batches A and B) run in lockstep in the same CTAs.
// Warp0 stages+publishes A, warp1 stages+publishes B in parallel; batch B's
// compute+stage executes inside batch A's fabric round-trip window and vice
// versa, hiding the exposed DSMEM latency that R4-R9 showed to be the invariant
// per-iteration cost. All per-batch arithmetic/tie-break rules are identical to
// the verified single-batch version.
__global__ void __cluster_dims__(CSZ,1,1) __launch_bounds__(FTH,1)
fps_kernel(float* __restrict__ newxyz){
  const int cid = blockIdx.x / CSZ;       // cluster id 0..3
  const int bA = 2*cid, bB = 2*cid + 1;
  const uint32_t rank = ctarank();
  const float* __restrict__ xsA = g_xs + bA*NPTS;
  const float* __restrict__ ysA = g_ys + bA*NPTS;
  const float* __restrict__ zsA = g_zs + bA*NPTS;
  const float* __restrict__ xsB = g_xs + bB*NPTS;
  const float* __restrict__ ysB = g_ys + bB*NPTS;
  const float* __restrict__ zsB = g_zs + bB*NPTS;
  const int t = threadIdx.x;
  const int lane = t & 31, wid = t >> 5;
  const int gi0 = rank*SLICE + t*PPT;

  __shared__ uint4 s_c4[2][NW];                         // [batch][warp] {vb,x,y,z}
  __shared__ unsigned long long s_exk[2][2][CSZ];       // [batch][par][rank]
  __shared__ unsigned long long s_exxy[2][2][CSZ];
  __shared__ unsigned long long s_exz[2][2][CSZ];
  __shared__ unsigned long long s_bar[2][2];            // [batch][par]

  // register-resident packed coords (4 pts/thread/batch)
  unsigned long long AX0,AX1,AY0,AY1,AZ0,AZ1, BX0,BX1,BY0,BY1,BZ0,BZ1;
  {
    const float4 x4 = *reinterpret_cast<const float4*>(xsA + gi0);
    const float4 y4 = *reinterpret_cast<const float4*>(ysA + gi0);
    const float4 z4 = *reinterpret_cast<const float4*>(zsA + gi0);
    AX0=pk2(x4.x,x4.y); AX1=pk2(x4.z,x4.w);
    AY0=pk2(y4.x,y4.y); AY1=pk2(y4.z,y4.w);
    AZ0=pk2(z4.x,z4.y); AZ1=pk2(z4.z,z4.w);
  }
  {
    const float4 x4 = *reinterpret_cast<const float4*>(xsB + gi0);
    const float4 y4 = *reinterpret_cast<const float4*>(ysB + gi0);
    const float4 z4 = *reinterpret_cast<const float4*>(zsB + gi0);
    BX0=pk2(x4.x,x4.y); BX1=pk2(x4.z,x4.w);
    BY0=pk2(y4.x,y4.y); BY1=pk2(y4.z,y4.w);
    BZ0=pk2(z4.x,z4.y); BZ1=pk2(z4.z,z4.w);
  }
  float dA0=1e10f,dA1=1e10f,dA2=1e10f,dA3=1e10f;
  float dB0=1e10f,dB1=1e10f,dB2=1e10f,dB3=1e10f;

  float cxA = xsA[0], cyA = ysA[0], czA = zsA[0];
  float cxB = xsB[0], cyB = ysB[0], czB = zsB[0];

  if (t == 0){
    mbar_init(smem_u32(&s_bar[0][0]), CSZ);
    mbar_init(smem_u32(&s_bar[0][1]), CSZ);
    mbar_init(smem_u32(&s_bar[1][0]), CSZ);
    mbar_init(smem_u32(&s_bar[1][1]), CSZ);
  }
  __syncthreads();
  cluster_sync_all();   // barrier inits visible cluster-wide before any remote arrive

  // stage-warp publish addresses (wid 0 -> batch A slots, wid 1 -> batch B slots)
  uint32_t pak[2], paxy[2], paz[2], pab[2];
  if (wid < 2 && lane < CSZ){
#pragma unroll
    for (int par = 0; par < 2; par++){
      pak [par] = mapa_rank(smem_u32(&s_exk [wid][par][rank]), (uint32_t)lane);
      paxy[par] = mapa_rank(smem_u32(&s_exxy[wid][par][rank]), (uint32_t)lane);
      paz [par] = mapa_rank(smem_u32(&s_exz [wid][par][rank]), (uint32_t)lane);
      pab [par] = mapa_rank(smem_u32(&s_bar [wid][par]),       (uint32_t)lane);
    }
  }

  for (int m = 0; m < NP; m++){
    if (rank == 0 && t == 0){
      const int pa = bA*NP + m;
      newxyz[3*pa+0]=cxA; newxyz[3*pa+1]=cyA; newxyz[3*pa+2]=czA;
      g_qx[pa]=cxA; g_qy[pa]=cyA; g_qz[pa]=czA;
      g_qn[pa]=__fadd_rn(__fadd_rn(__fmul_rn(cxA,cxA),__fmul_rn(cyA,cyA)),__fmul_rn(czA,czA));
      const int pb = bB*NP + m;
      newxyz[3*pb+0]=cxB; newxyz[3*pb+1]=cyB; newxyz[3*pb+2]=czB;
      g_qx[pb]=cxB; g_qy[pb]=cyB; g_qz[pb]=czB;
      g_qn[pb]=__fadd_rn(__fadd_rn(__fmul_rn(cxB,cxB),__fmul_rn(cyB,cyB)),__fmul_rn(czB,czB));
    }
    if (m == NP-1) break;

    // ---- batch A: packed no-FMA distance update + thread/warp argmax
    {
      const unsigned long long ncx=pk2(-cxA,-cxA), ncy=pk2(-cyA,-cyA), ncz=pk2(-czA,-czA);
      const unsigned long long dxa=add2(AX0,ncx), dya=add2(AY0,ncy), dza=add2(AZ0,ncz);
      unsigned long long sa=mul2(dxa,dxa); sa=add2(sa,mul2(dya,dya)); sa=add2(sa,mul2(dza,dza));
      const unsigned long long dxb=add2(AX1,ncx), dyb=add2(AY1,ncy), dzb=add2(AZ1,ncz);
      unsigned long long sb=mul2(dxb,dxb); sb=add2(sb,mul2(dyb,dyb)); sb=add2(sb,mul2(dzb,dzb));
      float la,ha,lb,hb; upk2(sa,la,ha); upk2(sb,lb,hb);
      dA0=fminf(dA0,la); dA1=fminf(dA1,ha); dA2=fminf(dA2,lb); dA3=fminf(dA3,hb);
      // thread-local argmax (strict > keeps first index)
      float v=dA0; int k=0;
      if (dA1>v){v=dA1;k=1;} if (dA2>v){v=dA2;k=2;} if (dA3>v){v=dA3;k=3;}
      const unsigned long long xp=(k&2)?AX1:AX0, yp=(k&2)?AY1:AY0, zp=(k&2)?AZ1:AZ0;
      float xl,xh,yl,yh,zl,zh; upk2(xp,xl,xh); upk2(yp,yl,yh); upk2(zp,zl,zh);
      const float bx=(k&1)?xh:xl, by=(k&1)?yh:yl, bz=(k&1)?zh:zl;
      const unsigned vb   = __float_as_uint(v);
      const unsigned wmax = __reduce_max_sync(0xffffffffu, vb);
      const unsigned bal  = __ballot_sync(0xffffffffu, vb == wmax);
      if (lane == __ffs(bal)-1)
        s_c4[0][wid] = make_uint4(wmax, __float_as_uint(bx), __float_as_uint(by), __float_as_uint(bz));
    }
    // ---- batch B: same
    {
      const unsigned long long ncx=pk2(-cxB,-cxB), ncy=pk2(-cyB,-cyB), ncz=pk2(-czB,-czB);
      const unsigned long long dxa=add2(BX0,ncx), dya=add2(BY0,ncy), dza=add2(BZ0,ncz);
      unsigned long long sa=mul2(dxa,dxa); sa=add2(sa,mul2(dya,dya)); sa=add2(sa,mul2(dza,dza));
      const unsigned long long dxb=add2(BX1,ncx), dyb=add2(BY1,ncy), dzb=add2(BZ1,ncz);
      unsigned long long sb=mul2(dxb,dxb); sb=add2(sb,mul2(dyb,dyb)); sb=add2(sb,mul2(dzb,dzb));
      float la,ha,lb,hb; upk2(sa,la,ha); upk2(sb,lb,hb);
      dB0=fminf(dB0,la); dB1=fminf(dB1,ha); dB2=fminf(dB2,lb); dB3=fminf(dB3,hb);
      float v=dB0; int k=0;
      if (dB1>v){v=dB1;k=1;} if (dB2>v){v=dB2;k=2;} if (dB3>v){v=dB3;k=3;}
      const unsigned long long xp=(k&2)?BX1:BX0, yp=(k&2)?BY1:BY0, zp=(k&2)?BZ1:BZ0;
      float xl,xh,yl,yh,zl,zh; upk2(xp,xl,xh); upk2(yp,yl,yh); upk2(zp,zl,zh);
      const float bx=(k&1)?xh:xl, by=(k&1)?yh:yl, bz=(k&1)?zh:zl;
      const unsigned vb   = __float_as_uint(v);
      const unsigned wmax = __reduce_max_sync(0xffffffffu, vb);
      const unsigned bal  = __ballot_sync(0xffffffffu, vb == wmax);
      if (lane == __ffs(bal)-1)
        s_c4[1][wid] = make_uint4(wmax, __float_as_uint(bx), __float_as_uint(by), __float_as_uint(bz));
    }
    __syncthreads();

    const int par = m & 1;
    const unsigned pty = (unsigned)((m >> 1) & 1);
    if (wid < 2){
      // warp0 stages batch A, warp1 stages batch B — in parallel
      const unsigned cv   = (lane < NW) ? s_c4[wid][lane].x : 0u;
      const unsigned bmax = __reduce_max_sync(0xffffffffu, cv);
      const unsigned bal2 = __ballot_sync(0xffffffffu, cv == bmax);
      const uint4 w = s_c4[wid][__ffs(bal2)-1];   // broadcast LDS of winner
      if (lane < CSZ){
        st_cl_u64(pak [par], (unsigned long long)w.x << 32);
        st_cl_u64(paxy[par], pk2(__uint_as_float(w.y), __uint_as_float(w.z)));
        st_cl_u64(paz [par], pk2(__uint_as_float(w.w), 0.f));
        mbar_arrive_rel_cluster(pab[par]);
      }
    }
    // ---- wait + combine A (B's compute/stage already filled A's fabric window)
    mbar_wait_acq_cta(smem_u32(&s_bar[0][par]), pty);
    {
      unsigned bh = (unsigned)(s_exk[0][par][0] >> 32); int br = 0;
#pragma unroll
      for (int r = 1; r < CSZ; r++){
        const unsigned h = (unsigned)(s_exk[0][par][r] >> 32);
        if (h > bh){ bh = h; br = r; }     // strict > keeps lowest rank
      }
      float du; upk2(s_exxy[0][par][br], cxA, cyA); upk2(s_exz[0][par][br], czA, du);
    }
    // ---- wait + combine B
    mbar_wait_acq_cta(smem_u32(&s_bar[1][par]), pty);
    {
      unsigned bh = (unsigned)(s_exk[1][par][0] >> 32); int br = 0;
#pragma unroll
      for (int r = 1; r < CSZ; r++){
        const unsigned h = (unsigned)(s_exk[1][par][r] >> 32);
        if (h > bh){ bh = h; br = r; }
      }
      float du; upk2(s_exxy[1][par][br], cxB, cyB); upk2(s_exz[1][par][br], czB, du);
    }
  }
  cluster_sync_all();
}

// ---------------- ball query: one warp per (b,p), 64-pt unrolled scan ----------------
__global__ __launch_bounds__(256) void ballquery_kernel(){
  const int warp = (blockIdx.x*blockDim.x + threadIdx.x) >> 5;   // 0..8191
  const int lane = threadIdx.x & 31;
  const int b = warp >> 10;
  const float* __restrict__ xs = g_xs + b*NPTS;
  const float* __restrict__ ys = g_ys + b*NPTS;
  const float* __restrict__ zs = g_zs + b*NPTS;
  const float* __restrict__ xn = g_xn + b*NPTS;
  const float qx = g_qx[warp], qy = g_qy[warp], qz = g_qz[warp], qn = g_qn[warp];
  int* __restrict__ o0 = g_idx0 + warp*16;
  int* __restrict__ o1 = g_idx1 + warp*32;
  int cnt0=0, cnt1=0, f0=0, f1=0;
  const unsigned lmask = (1u << lane) - 1u;

  for (int n0=0; n0<NPTS; n0+=64){
    const int na = n0 + lane, nb2 = n0 + 32 + lane;
    const float xa = xs[na],  ya = ys[na],  za = zs[na],  pa = xn[na];
    const float xb = xs[nb2], yb = ys[nb2], zb = zs[nb2], pb = xn[nb2];
    const float dota = fmaf(qx,xa, fmaf(qy,ya, qz*za));
    const float dotb = fmaf(qx,xb, fmaf(qy,yb, qz*zb));
    const float d2a  = __fadd_rn(__fadd_rn(qn, pa), -2.f*dota);
    const float d2b  = __fadd_rn(__fadd_rn(qn, pb), -2.f*dotb);

    {
      const bool h0 = d2a < 0.25f, h1 = d2a < 1.0f;
      const unsigned m0 = __ballot_sync(0xffffffffu, h0);
      const unsigned m1 = __ballot_sync(0xffffffffu, h1);
      if (cnt0 < 16 && m0){
        if (cnt0 == 0) f0 = n0 + __ffs(m0) - 1;
        const int r = __popc(m0 & lmask);
        if (h0 && cnt0 + r < 16) o0[cnt0 + r] = na;
        cnt0 = min(16, cnt0 + __popc(m0));
      }
      if (cnt1 < 32 && m1){
        if (cnt1 == 0) f1 = n0 + __ffs(m1) - 1;
        const int r = __popc(m1 & lmask);
        if (h1 && cnt1 + r < 32) o1[cnt1 + r] = na;
        cnt1 = min(32, cnt1 + __popc(m1));
      }
    }
    {
      const bool h0 = d2b < 0.25f, h1 = d2b < 1.0f;
      const unsigned m0 = __ballot_sync(0xffffffffu, h0);
      const unsigned m1 = __ballot_sync(0xffffffffu, h1);
      if (cnt0 < 16 && m0){
        if (cnt0 == 0) f0 = n0 + 32 + __ffs(m0) - 1;
        const int r = __popc(m0 & lmask);
        if (h0 && cnt0 + r < 16) o0[cnt0 + r] = nb2;
        cnt0 = min(16, cnt0 + __popc(m0));
      }
      if (cnt1 < 32 && m1){
        if (cnt1 == 0) f1 = n0 + 32 + __ffs(m1) - 1;
        const int r = __popc(m1 & lmask);
        if (h1 && cnt1 + r < 32) o1[cnt1 + r] = nb2;
        cnt1 = min(32, cnt1 + __popc(m1));
      }
    }
    if (cnt0 >= 16 && cnt1 >= 32) break;
  }
  if (lane >= cnt0 && lane < 16) o0[lane] = f0;   // pad with first hit (0 if none)
  if (lane >= cnt1)              o1[lane] = f1;
}

// ---------------- fused group + 2-layer MLP + maxpool (device body) ----------------
template<int S, int C1O, int C2O, int COFF>
__device__ __forceinline__ void mlp_body(
    int bp, char* smraw,
    const float* __restrict__ feats,
    const float* __restrict__ s1, const float* __restrict__ b1,
    const float* __restrict__ w2, const float* __restrict__ s2, const float* __restrict__ b2,
    float* __restrict__ outf)
{
  const int b = bp >> 10, p = bp & (NP-1);
  const int t = threadIdx.x;
  float* xin = (float*)smraw;            // 36*S
  float* h1s = xin + 36*S;               // C1O*S
  int*   sidx= (int*)(h1s + C1O*S);      // S
  float* red = (float*)(sidx + S);       // 128

  const int*   __restrict__ idxb = (COFF==0) ? g_idx0 : g_idx1;
  const float* __restrict__ w1p  = (COFF==0) ? g_w0p  : g_w1p;

  if (t < S) sidx[t] = idxb[bp*S + t];
  const float cx = g_qx[bp], cy = g_qy[bp], cz = g_qz[bp];
  const float* __restrict__ xsb = g_xs + b*NPTS;
  const float* __restrict__ ysb = g_ys + b*NPTS;
  const float* __restrict__ zsb = g_zs + b*NPTS;
  const float* __restrict__ fb  = feats + b*CIN*NPTS;
  __syncthreads();

  for (int e=t; e<35*S; e+=128){
    const int c = e / S, s = e - c*S;
    const int n = sidx[s];
    float v;
    if      (c==0) v = xsb[n]-cx;
    else if (c==1) v = ysb[n]-cy;
    else if (c==2) v = zsb[n]-cz;
    else           v = fb[(c-3)*NPTS + n];
    xin[c*S+s] = v;
  }
  if (t < S) xin[35*S+t] = 0.f;
  __syncthreads();

  // ---- layer 1: 35->C1O with packed f32x2 FMA (bit-exact vs scalar fmaf)
  constexpr int SPT1  = C1O*S/128;
  constexpr int NAC1  = SPT1/2;
  constexpr int G1    = S/SPT1;
  {
    const int o  = t / G1;
    const int sb = (t - o*G1)*SPT1;
    unsigned long long acc[NAC1];
#pragma unroll
    for (int i=0;i<NAC1;i++) acc[i]=0ull;
    const float* wr = w1p + o*36;
#pragma unroll 3
    for (int in=0; in<36; in+=4){
      const float4 w4 = *reinterpret_cast<const float4*>(wr+in);
      const float wv[4] = {w4.x,w4.y,w4.z,w4.w};
#pragma unroll
      for (int j=0;j<4;j++){
        const unsigned long long w2v = pk2(wv[j], wv[j]);
        const unsigned long long* xp =
          reinterpret_cast<const unsigned long long*>(&xin[(in+j)*S + sb]);
#pragma unroll
        for (int q=0;q<NAC1;q++) acc[q] = fma2(w2v, xp[q], acc[q]);
      }
    }
    const float sc = s1[o], bb = b1[o];
#pragma unroll
    for (int q=0;q<NAC1;q++){
      float a0, a1; upk2(acc[q], a0, a1);
      h1s[o*S + sb + 2*q    ] = fmaxf(fmaf(a0,sc,bb), 0.f);
      h1s[o*S + sb + 2*q + 1] = fmaxf(fmaf(a1,sc,bb), 0.f);
    }
  }
  __syncthreads();

  // ---- layer 2: C1O->C2O + ReLU + maxpool over S (packed f32x2 FMA)
  constexpr int SPT2 = C2O*S/128;
  constexpr int NAC2 = SPT2/2;
  constexpr int G2   = S/SPT2;
  {
    const int o  = t / G2;
    const int sb = (t - o*G2)*SPT2;
    unsigned long long acc[NAC2];
#pragma unroll
    for (int i=0;i<NAC2;i++) acc[i]=0ull;
    const float* wr = w2 + o*C1O;
#pragma unroll 4
    for (int in=0; in<C1O; in+=4){
      const float4 w4 = *reinterpret_cast<const float4*>(wr+in);
      const float wv[4] = {w4.x,w4.y,w4.z,w4.w};
#pragma unroll
      for (int j=0;j<4;j++){
        const unsigned long long w2v = pk2(wv[j], wv[j]);
        const unsigned long long* xp =
          reinterpret_cast<const unsigned long long*>(&h1s[(in+j)*S + sb]);
#pragma unroll
        for (int q=0;q<NAC2;q++) acc[q] = fma2(w2v, xp[q], acc[q]);
      }
    }
    const float sc = s2[o], bb = b2[o];
    float vm = 0.f;   // ReLU => max over relu == max(0, max(pre))
#pragma unroll
    for (int q=0;q<NAC2;q++){
      float a0, a1; upk2(acc[q], a0, a1);
      vm = fmaxf(vm, fmaf(a0,sc,bb));
      vm = fmaxf(vm, fmaf(a1,sc,bb));
    }
    if (G2 == 1){
      outf[(b*192 + COFF + o)*NP + p] = vm;
    } else {
      red[t] = vm;
      __syncthreads();
      if (t < C2O)
        outf[(b*192 + COFF + t)*NP + p] = fmaxf(red[t*G2], red[t*G2+1]);
    }
  }
}

// ---------------- merged MLP launch: both branches in one grid (overlap) ----------------
__global__ __launch_bounds__(128) void mlp_merged(
    const float* __restrict__ feats,
    const float* __restrict__ s00, const float* __restrict__ b00,
    const float* __restrict__ w01, const float* __restrict__ s01, const float* __restrict__ b01,
    const float* __restrict__ s10, const float* __restrict__ b10,
    const float* __restrict__ w11, const float* __restrict__ s11, const float* __restrict__ b11,
    float* __restrict__ outf)
{
  extern __shared__ char smraw[];
  if (blockIdx.x < NB*NP)
    mlp_body<16,32, 64, 0>(blockIdx.x,          smraw, feats, s00,b00, w01,s01,b01, outf);
  else
    mlp_body<32,64,128,64>(blockIdx.x - NB*NP,  smraw, feats, s10,b10, w11,s11,b11, outf);
}

// dynamic smem: branch1 is larger: (36*32 + 64*32)*4 + 32*4 + 128*4 bytes
#define MLP_SMEM ((36*32 + 64*32)*4 + 32*4 + 128*4)

// ---------------- launch ----------------
extern "C" void kernel_launch(void* const* d_in, const int* in_sizes, int n_in,
                              void* d_out, int out_size) {
  const float* xyz   = (const float*)d_in[0];
  const float* feats = (const float*)d_in[1];
  const float* w00 = (const float*)d_in[2];
  const float* s00 = (const float*)d_in[3];
  const float* b00 = (const float*)d_in[4];
  const float* w01 = (const float*)d_in[5];
  const float* s01 = (const float*)d_in[6];
  const float* b01 = (const float*)d_in[7];
  const float* w10 = (const float*)d_in[8];
  const float* s10 = (const float*)d_in[9];
  const float* b10 = (const float*)d_in[10];
  const float* w11 = (const float*)d_in[11];
  const float* s11 = (const float*)d_in[12];
  const float* b11 = (const float*)d_in[13];
  float* out = (float*)d_out;

  prep_soa<<<(NB*NPTS+255)/256, 256>>>(xyz);
  prep_w<<<1,256>>>(w00, w10);
  fps_kernel<<<(NB/2)*CSZ, FTH>>>(out);                // 4 clusters x 8 CTAs, 2 batches each
  ballquery_kernel<<<(NB*NP)/8, 256>>>();
  float* outf = out + NB*NP*3;                         // features (B,192,P)
  mlp_merged<<<2*NB*NP, 128, MLP_SMEM>>>(feats, s00,b00, w01,s01,b01,
                                         s10,b10, w11,s11,b11, outf);
}